// round 2
// baseline (speedup 1.0000x reference)
#include <cuda_runtime.h>

// Problem constants
#define G        25
#define KIN      15
#define KOUT     3
#define XDIM     (G * KIN)        // 375
#define ODIM     (G * KOUT)       // 75
#define WSIZE    (G * KOUT * KIN) // 1125

#define ROWS_PER_BLOCK 16
#define THREADS        256

__global__ __launch_bounds__(THREADS)
void mlp_rsna4_kernel(const float* __restrict__ x,
                      const float* __restrict__ W,
                      const int*   __restrict__ k_idx,
                      const int*   __restrict__ v_idx,
                      float* __restrict__ out)
{
    __shared__ float sx[ROWS_PER_BLOCK * XDIM];  // 6000 floats = 24000 B
    __shared__ float sW[WSIZE];                  // 4500 B
    __shared__ int   sk[XDIM];                   // 1500 B
    __shared__ int   sv[ODIM];                   // 300 B

    const int tid = threadIdx.x;
    const long long row0 = (long long)blockIdx.x * ROWS_PER_BLOCK;

    // ---- Stage x tile: contiguous span, vectorized float4, coalesced ----
    // Tile span = 16*375*4 = 24000 bytes, 16B-divisible, so base is aligned
    // for float4 as long as x itself is 16B-aligned (cudaMalloc guarantees 256B).
    {
        const float4* __restrict__ xin = (const float4*)(x + row0 * XDIM);
        float4* sx4 = (float4*)sx;
        #pragma unroll
        for (int i = tid; i < (ROWS_PER_BLOCK * XDIM) / 4; i += THREADS)
            sx4[i] = xin[i];
    }

    // ---- Stage W and index tables (strided: tables exceed THREADS) ----
    for (int i = tid; i < WSIZE; i += THREADS) sW[i] = W[i];
    for (int i = tid; i < XDIM;  i += THREADS) sk[i] = k_idx[i];   // <-- R1 bugfix
    for (int i = tid; i < ODIM;  i += THREADS) sv[i] = v_idx[i];

    __syncthreads();

    // ---- Compute: ROWS_PER_BLOCK * ODIM = 1200 outputs over 256 threads ----
    for (int idx = tid; idx < ROWS_PER_BLOCK * ODIM; idx += THREADS) {
        const int r = idx / ODIM;
        const int j = idx - r * ODIM;       // output slot 0..74
        const int g = j / KOUT;
        const int o = j - g * KOUT;

        const float* __restrict__ xr = sx + r * XDIM;
        const float* __restrict__ wr = sW + (g * KOUT + o) * KIN;
        const int*   __restrict__ ki = sk + g * KIN;

        float acc = 0.0f;
        #pragma unroll
        for (int i = 0; i < KIN; i++)
            acc = fmaf(xr[ki[i]], wr[i], acc);

        // v_idx is a permutation covering all 75 slots -> every output written
        out[(row0 + r) * ODIM + sv[j]] = acc;
    }
}

extern "C" void kernel_launch(void* const* d_in, const int* in_sizes, int n_in,
                              void* d_out, int out_size)
{
    const float* x     = (const float*)d_in[0];
    const float* W     = (const float*)d_in[1];
    const int*   k_idx = (const int*)d_in[2];
    const int*   v_idx = (const int*)d_in[3];
    float* out = (float*)d_out;

    const int b_rows  = in_sizes[0] / XDIM;            // 262144
    const int nblocks = b_rows / ROWS_PER_BLOCK;       // 16384
    mlp_rsna4_kernel<<<nblocks, THREADS>>>(x, W, k_idx, v_idx, out);
}

// round 3
// speedup vs baseline: 1.6597x; 1.6597x over previous
#include <cuda_runtime.h>

#define G        25
#define KIN      15
#define KOUT     3
#define XDIM     (G * KIN)        // 375
#define ODIM     (G * KOUT)       // 75

#define ROWS_PER_TILE  32
#define THREADS        256
#define NWARPS         (THREADS / 32)
#define ROWS_PER_WARP  (ROWS_PER_TILE / NWARPS)   // 4
#define GRID_CTAS      444                         // 3 per SM * 148

__global__ __launch_bounds__(THREADS, 3)
void mlp_rsna4_kernel(const float* __restrict__ x,
                      const float* __restrict__ W,
                      const int*   __restrict__ k_idx,
                      const int*   __restrict__ v_idx,
                      float* __restrict__ out,
                      int ntiles)
{
    __shared__ float sx[ROWS_PER_TILE * XDIM];   // 12000 floats = 48000 B

    const int tid  = threadIdx.x;
    const int wrp  = tid >> 5;
    const int lane = tid & 31;
    const bool active = (lane < G);
    const int g = lane;   // group owned by this lane (valid iff active)

    // ---- Per-thread persistent state: W row, gather/scatter indices ----
    float wreg[KOUT * KIN];   // 45
    int   ki[KIN];            // 15
    int   vi[KOUT];           // 3
    if (active) {
        #pragma unroll
        for (int i = 0; i < KOUT * KIN; i++) wreg[i] = W[g * KOUT * KIN + i];
        #pragma unroll
        for (int i = 0; i < KIN; i++) ki[i] = k_idx[g * KIN + i];
        #pragma unroll
        for (int o = 0; o < KOUT; o++) vi[o] = v_idx[g * KOUT + o];
    }

    // ---- Grid-stride loop over 32-row tiles ----
    for (int tile = blockIdx.x; tile < ntiles; tile += gridDim.x) {
        const long long row0 = (long long)tile * ROWS_PER_TILE;

        __syncthreads();   // previous compute done before overwriting sx

        // Stage tile: contiguous 48000-byte span, float4, fully coalesced
        {
            const float4* __restrict__ xin = (const float4*)(x + row0 * XDIM);
            float4* sx4 = (float4*)sx;
            #pragma unroll
            for (int i = tid; i < (ROWS_PER_TILE * XDIM) / 4; i += THREADS)
                sx4[i] = xin[i];
        }
        __syncthreads();

        if (active) {
            #pragma unroll
            for (int rr = 0; rr < ROWS_PER_WARP; rr++) {
                const int r = wrp + rr * NWARPS;
                const float* __restrict__ xr = sx + r * XDIM;

                float a0 = 0.f, a1 = 0.f, a2 = 0.f;
                #pragma unroll
                for (int i = 0; i < KIN; i++) {
                    const float xv = xr[ki[i]];      // conflict-free: stride 15 vs 32 banks
                    a0 = fmaf(xv, wreg[i],            a0);
                    a1 = fmaf(xv, wreg[KIN + i],      a1);
                    a2 = fmaf(xv, wreg[2 * KIN + i],  a2);
                }

                const long long obase = (row0 + r) * ODIM;
                out[obase + vi[0]] = a0;
                out[obase + vi[1]] = a1;
                out[obase + vi[2]] = a2;
            }
        }
    }
}

extern "C" void kernel_launch(void* const* d_in, const int* in_sizes, int n_in,
                              void* d_out, int out_size)
{
    const float* x     = (const float*)d_in[0];
    const float* W     = (const float*)d_in[1];
    const int*   k_idx = (const int*)d_in[2];
    const int*   v_idx = (const int*)d_in[3];
    float* out = (float*)d_out;

    const int b_rows = in_sizes[0] / XDIM;          // 262144
    const int ntiles = b_rows / ROWS_PER_TILE;      // 8192

    int grid = GRID_CTAS;
    if (grid > ntiles) grid = ntiles;
    mlp_rsna4_kernel<<<grid, THREADS>>>(x, W, k_idx, v_idx, out, ntiles);
}

// round 4
// speedup vs baseline: 1.8756x; 1.1301x over previous
#include <cuda_runtime.h>
#include <cstdint>

#define G        25
#define KIN      15
#define KOUT     3
#define XDIM     (G * KIN)        // 375
#define ODIM     (G * KOUT)       // 75

#define ROWS_PER_TILE  16
#define THREADS        256
#define NWARPS         (THREADS / 32)
#define ROWS_PER_WARP  (ROWS_PER_TILE / NWARPS)   // 2
#define TILE_F4        (ROWS_PER_TILE * XDIM / 4) // 1500 float4 per tile
#define GRID_CTAS      444                         // 3 per SM * 148

__device__ __forceinline__ void cp_async16(void* smem_dst, const void* gmem_src) {
    uint32_t s = (uint32_t)__cvta_generic_to_shared(smem_dst);
    asm volatile("cp.async.cg.shared.global [%0], [%1], 16;\n" :: "r"(s), "l"(gmem_src));
}
__device__ __forceinline__ void cp_async_commit() {
    asm volatile("cp.async.commit_group;\n" ::: "memory");
}
__device__ __forceinline__ void cp_async_wait1() {
    asm volatile("cp.async.wait_group 1;\n" ::: "memory");
}

__global__ __launch_bounds__(THREADS, 3)
void mlp_rsna4_kernel(const float* __restrict__ x,
                      const float* __restrict__ W,
                      const int*   __restrict__ k_idx,
                      const int*   __restrict__ v_idx,
                      float* __restrict__ out,
                      int ntiles)
{
    __shared__ float sx[2][ROWS_PER_TILE * XDIM];   // 2 * 24000 B = 48 KB

    const int tid  = threadIdx.x;
    const int wrp  = tid >> 5;
    const int lane = tid & 31;
    const bool active = (lane < G);
    const int g = lane;

    // ---- Per-thread persistent state: W row, gather/scatter indices ----
    float wreg[KOUT * KIN];   // 45
    int   ki[KIN];            // 15
    int   vi[KOUT];           // 3
    if (active) {
        #pragma unroll
        for (int i = 0; i < KOUT * KIN; i++) wreg[i] = W[g * KOUT * KIN + i];
        #pragma unroll
        for (int i = 0; i < KIN; i++) ki[i] = k_idx[g * KIN + i];
        #pragma unroll
        for (int o = 0; o < KOUT; o++) vi[o] = v_idx[g * KOUT + o];
    }

    // ---- Prefetch first tile into buffer 0 ----
    int tile = blockIdx.x;
    int buf = 0;
    if (tile < ntiles) {
        const float4* __restrict__ xin = (const float4*)(x + (long long)tile * ROWS_PER_TILE * XDIM);
        #pragma unroll
        for (int i = tid; i < TILE_F4; i += THREADS)
            cp_async16(&sx[0][i * 4], xin + i);
    }
    cp_async_commit();

    // ---- Pipelined grid-stride loop ----
    for (; tile < ntiles; tile += gridDim.x) {
        const int next = tile + gridDim.x;
        if (next < ntiles) {
            const float4* __restrict__ xin = (const float4*)(x + (long long)next * ROWS_PER_TILE * XDIM);
            #pragma unroll
            for (int i = tid; i < TILE_F4; i += THREADS)
                cp_async16(&sx[buf ^ 1][i * 4], xin + i);
        }
        cp_async_commit();        // commit next-tile group (may be empty)
        cp_async_wait1();         // current tile's group is complete
        __syncthreads();          // staged data visible to all warps

        if (active) {
            const long long row0 = (long long)tile * ROWS_PER_TILE;
            #pragma unroll
            for (int rr = 0; rr < ROWS_PER_WARP; rr++) {
                const int r = wrp * ROWS_PER_WARP + rr;
                const float* __restrict__ xr = sx[buf] + r * XDIM;

                float a0 = 0.f, a1 = 0.f, a2 = 0.f;
                #pragma unroll
                for (int i = 0; i < KIN; i++) {
                    const float xv = xr[ki[i]];      // stride-15 gather: conflict-free
                    a0 = fmaf(xv, wreg[i],            a0);
                    a1 = fmaf(xv, wreg[KIN + i],      a1);
                    a2 = fmaf(xv, wreg[2 * KIN + i],  a2);
                }

                const long long obase = (row0 + r) * ODIM;
                out[obase + vi[0]] = a0;
                out[obase + vi[1]] = a1;
                out[obase + vi[2]] = a2;
            }
        }

        __syncthreads();          // all reads of sx[buf] done before it is restaged
        buf ^= 1;
    }
}

extern "C" void kernel_launch(void* const* d_in, const int* in_sizes, int n_in,
                              void* d_out, int out_size)
{
    const float* x     = (const float*)d_in[0];
    const float* W     = (const float*)d_in[1];
    const int*   k_idx = (const int*)d_in[2];
    const int*   v_idx = (const int*)d_in[3];
    float* out = (float*)d_out;

    const int b_rows = in_sizes[0] / XDIM;          // 262144
    const int ntiles = b_rows / ROWS_PER_TILE;      // 16384

    int grid = GRID_CTAS;
    if (grid > ntiles) grid = ntiles;
    mlp_rsna4_kernel<<<grid, THREADS>>>(x, W, k_idx, v_idx, out, ntiles);
}

// round 5
// speedup vs baseline: 1.9083x; 1.0174x over previous
#include <cuda_runtime.h>
#include <cstdint>

#define G        25
#define KIN      15
#define KOUT     3
#define XDIM     (G * KIN)        // 375
#define ODIM     (G * KOUT)       // 75

#define ROWS_PER_TILE  16
#define THREADS        256
#define NWARPS         (THREADS / 32)
#define ROWS_PER_WARP  (ROWS_PER_TILE / NWARPS)   // 2
#define TILE_F4        (ROWS_PER_TILE * XDIM / 4) // 1500 float4 per tile
#define OUT_F4         (ROWS_PER_TILE * ODIM / 4) // 300 float4 per tile
#define GRID_CTAS      444                         // 3 per SM * 148

__device__ __forceinline__ void cp_async16(void* smem_dst, const void* gmem_src) {
    uint32_t s = (uint32_t)__cvta_generic_to_shared(smem_dst);
    asm volatile("cp.async.cg.shared.global [%0], [%1], 16;\n" :: "r"(s), "l"(gmem_src));
}
__device__ __forceinline__ void cp_async_commit() {
    asm volatile("cp.async.commit_group;\n" ::: "memory");
}
__device__ __forceinline__ void cp_async_wait1() {
    asm volatile("cp.async.wait_group 1;\n" ::: "memory");
}

__global__ __launch_bounds__(THREADS, 3)
void mlp_rsna4_kernel(const float* __restrict__ x,
                      const float* __restrict__ W,
                      const int*   __restrict__ k_idx,
                      const int*   __restrict__ v_idx,
                      float* __restrict__ out,
                      int ntiles)
{
    __shared__ float sx[2][ROWS_PER_TILE * XDIM];   // 48000 B
    __shared__ float sout[ROWS_PER_TILE * ODIM];    //  4800 B

    const int tid  = threadIdx.x;
    const int wrp  = tid >> 5;
    const int lane = tid & 31;
    const bool active = (lane < G);
    const int g = lane;

    // ---- Per-thread persistent state: W row, gather/scatter indices ----
    float wreg[KOUT * KIN];   // 45
    int   ki[KIN];            // 15
    int   vi[KOUT];           // 3
    if (active) {
        #pragma unroll
        for (int i = 0; i < KOUT * KIN; i++) wreg[i] = W[g * KOUT * KIN + i];
        #pragma unroll
        for (int i = 0; i < KIN; i++) ki[i] = k_idx[g * KIN + i];
        #pragma unroll
        for (int o = 0; o < KOUT; o++) vi[o] = v_idx[g * KOUT + o];
    }

    // ---- Prefetch first tile into buffer 0 ----
    int tile = blockIdx.x;
    int buf = 0;
    if (tile < ntiles) {
        const float4* __restrict__ xin = (const float4*)(x + (long long)tile * ROWS_PER_TILE * XDIM);
        #pragma unroll
        for (int i = tid; i < TILE_F4; i += THREADS)
            cp_async16(&sx[0][i * 4], xin + i);
    }
    cp_async_commit();

    // ---- Pipelined grid-stride loop ----
    for (; tile < ntiles; tile += gridDim.x) {
        const int next = tile + gridDim.x;
        if (next < ntiles) {
            const float4* __restrict__ xin = (const float4*)(x + (long long)next * ROWS_PER_TILE * XDIM);
            #pragma unroll
            for (int i = tid; i < TILE_F4; i += THREADS)
                cp_async16(&sx[buf ^ 1][i * 4], xin + i);
        }
        cp_async_commit();        // commit next-tile group (may be empty)
        cp_async_wait1();         // current tile's group is complete
        __syncthreads();          // staged x visible; prior STG-from-sout phase done

        if (active) {
            #pragma unroll
            for (int rr = 0; rr < ROWS_PER_WARP; rr++) {
                const int r = wrp * ROWS_PER_WARP + rr;
                const float* __restrict__ xr = sx[buf] + r * XDIM;

                float a0 = 0.f, a1 = 0.f, a2 = 0.f;
                #pragma unroll
                for (int i = 0; i < KIN; i++) {
                    const float xv = xr[ki[i]];      // stride-15 gather: conflict-free
                    a0 = fmaf(xv, wreg[i],            a0);
                    a1 = fmaf(xv, wreg[KIN + i],      a1);
                    a2 = fmaf(xv, wreg[2 * KIN + i],  a2);
                }

                // Scatter into smem staging (stride-3 across lanes: conflict-free)
                float* __restrict__ so = sout + r * ODIM;
                so[vi[0]] = a0;
                so[vi[1]] = a1;
                so[vi[2]] = a2;
            }
        }

        __syncthreads();          // sout fully written

        // Coalesced vectorized flush: 4800 B contiguous span per tile
        {
            const float4* __restrict__ so4 = (const float4*)sout;
            float4* __restrict__ o4 =
                (float4*)(out + (long long)tile * ROWS_PER_TILE * ODIM);
            #pragma unroll
            for (int i = tid; i < OUT_F4; i += THREADS)
                o4[i] = so4[i];
        }

        __syncthreads();          // sx[buf] + sout reads done before restage/rewrite
        buf ^= 1;
    }
}

extern "C" void kernel_launch(void* const* d_in, const int* in_sizes, int n_in,
                              void* d_out, int out_size)
{
    const float* x     = (const float*)d_in[0];
    const float* W     = (const float*)d_in[1];
    const int*   k_idx = (const int*)d_in[2];
    const int*   v_idx = (const int*)d_in[3];
    float* out = (float*)d_out;

    const int b_rows = in_sizes[0] / XDIM;          // 262144
    const int ntiles = b_rows / ROWS_PER_TILE;      // 16384

    int grid = GRID_CTAS;
    if (grid > ntiles) grid = ntiles;
    mlp_rsna4_kernel<<<grid, THREADS>>>(x, W, k_idx, v_idx, out, ntiles);
}